// round 1
// baseline (speedup 1.0000x reference)
#include <cuda_runtime.h>
#include <math.h>

// ---- fixed problem shapes ----
#define GG   512      // graphs
#define NPG  128      // nodes per graph
#define NN   65536    // total nodes
#define DD   512      // feature dim
#define KC   1024     // codebook size
#define HHID 128      // mlp hidden
#define TCLS 10       // classes

// ---- device scratch (allocation-free workaround) ----
static __device__ float g_ct [KC*DD];   // codebook_transformed
static __device__ float g_cs [KC*DD];   // sigmoid(ct)
static __device__ float g_c1 [KC*DD];   // counter_matrix @ cs
static __device__ float g_ccb[KC*DD];   // causal_cb
static __device__ float g_xcb[KC*DD];   // counter_cb
static __device__ float g_cbn[KC];      // ||causal_cb_k||^2
static __device__ int   g_idx[NN];      // argmin code per node
static __device__ float g_invnx[NN];    // 1/max(||x_n||,1e-12)
static __device__ float g_invnz[NN];    // 1/max(||z_n||,1e-12)

// ---- output offsets (floats) in tuple order ----
#define O_CPRE 0LL
#define O_KPRE 5120LL
#define O_YPRE 10240LL
#define O_AO   15360LL
#define O_AR   8403968LL
#define O_Z    16792576LL
#define O_X    50347008LL
#define O_CD   83901440LL
#define O_CM   84950016LL
#define O_PC   85998592LL
#define O_PX   86260736LL

__device__ __forceinline__ float sigm(float v) { return 1.f / (1.f + expf(-v)); }

// ============================================================
// K1: per-codebook-row 2-layer MLP: ct = fc2(sigmoid(fc1(cb))), cs = sigmoid(ct)
// grid: KC blocks x 128 threads
// ============================================================
__global__ void mlp_kernel(const float* __restrict__ cbin,
                           const float* __restrict__ fc1w, const float* __restrict__ fc1b,
                           const float* __restrict__ fc2w, const float* __restrict__ fc2b) {
    __shared__ float row[DD];
    __shared__ float hs[HHID];
    int k = blockIdx.x, t = threadIdx.x;
    for (int d = t; d < DD; d += 128) row[d] = cbin[(size_t)k*DD + d];
    __syncthreads();
    float acc = fc1b[t];
    const float* w = fc1w + (size_t)t*DD;
    #pragma unroll 8
    for (int d = 0; d < DD; d++) acc += row[d] * w[d];
    hs[t] = sigm(acc);
    __syncthreads();
    for (int d = t; d < DD; d += 128) {
        float a = fc2b[d];
        const float* w2 = fc2w + (size_t)d*HHID;
        #pragma unroll 8
        for (int h = 0; h < HHID; h++) a += hs[h] * w2[h];
        g_ct[(size_t)k*DD + d] = a;
        g_cs[(size_t)k*DD + d] = sigm(a);
    }
}

// ============================================================
// K2: write causal_diag (diag only) and counter_matrix (off-diag) outputs
// ============================================================
__global__ void diag_kernel(const float* __restrict__ causal, float* __restrict__ out) {
    int i = blockIdx.x;
    size_t base = (size_t)i * KC;
    for (int j = threadIdx.x; j < KC; j += blockDim.x) {
        float c = causal[base + j];
        bool dg = (j == i);
        out[O_CD + base + j] = dg ? c : 0.f;
        out[O_CM + base + j] = dg ? 0.f : c;
    }
}

// ============================================================
// K3: C[1024,512] = patch(causal) @ B  (diag patched; optional row scale by diag(causal))
//   mode 0: g_c1  = (diag->0 causal) @ g_cs
//   mode 1: g_ccb = (diag->1 causal) @ (diag(causal) .* g_cs rows)
//   mode 2: g_xcb = (diag->1 causal) @ g_c1
// grid (8,16), 256 threads, BM=BN=64, BK=16, 4x4 per thread
// ============================================================
__global__ __launch_bounds__(256) void gemm_cc(const float* __restrict__ A, int mode) {
    const float* B = (mode == 2) ? g_c1 : g_cs;
    float* C = (mode == 0) ? g_c1 : (mode == 1 ? g_ccb : g_xcb);
    float diag_patch = (mode == 0) ? 0.f : 1.f;
    bool scale = (mode == 1);

    __shared__ float As[16][64];
    __shared__ float Bs[16][64];
    int tid = threadIdx.x, tx = tid & 15, ty = tid >> 4;
    int bm = blockIdx.y * 64, bn = blockIdx.x * 64;
    float acc[4][4] = {};
    for (int k0 = 0; k0 < KC; k0 += 16) {
        #pragma unroll
        for (int p = 0; p < 4; p++) {
            int e = tid + p * 256;
            int r = e >> 4, kk = e & 15;
            int grow = bm + r, gk = k0 + kk;
            As[kk][r] = (grow == gk) ? diag_patch : A[(size_t)grow*KC + gk];
        }
        #pragma unroll
        for (int p = 0; p < 4; p++) {
            int e = tid + p * 256;
            int kk = e >> 6, c = e & 63;
            int gk = k0 + kk;
            float bv = B[(size_t)gk*DD + bn + c];
            if (scale) bv *= A[(size_t)gk*KC + gk];
            Bs[kk][c] = bv;
        }
        __syncthreads();
        #pragma unroll
        for (int kk = 0; kk < 16; kk++) {
            float4 a = *(const float4*)&As[kk][ty*4];
            float4 b = *(const float4*)&Bs[kk][tx*4];
            float av[4] = {a.x, a.y, a.z, a.w};
            float bv[4] = {b.x, b.y, b.z, b.w};
            #pragma unroll
            for (int i = 0; i < 4; i++)
                #pragma unroll
                for (int j = 0; j < 4; j++)
                    acc[i][j] += av[i] * bv[j];
        }
        __syncthreads();
    }
    #pragma unroll
    for (int i = 0; i < 4; i++) {
        float4 v = make_float4(acc[i][0], acc[i][1], acc[i][2], acc[i][3]);
        *(float4*)&C[(size_t)(bm + ty*4 + i)*DD + bn + tx*4] = v;
    }
}

// ============================================================
// K4: g_cbn[k] = ||causal_cb_k||^2
// ============================================================
__global__ void cbn_kernel() {
    int k = blockIdx.x;
    float s = 0.f;
    for (int d = threadIdx.x; d < DD; d += 128) {
        float v = g_ccb[(size_t)k*DD + d];
        s += v * v;
    }
    #pragma unroll
    for (int off = 16; off; off >>= 1) s += __shfl_xor_sync(~0u, s, off);
    __shared__ float red[4];
    if ((threadIdx.x & 31) == 0) red[threadIdx.x >> 5] = s;
    __syncthreads();
    if (threadIdx.x == 0) g_cbn[k] = red[0] + red[1] + red[2] + red[3];
}

// ============================================================
// K5: fused distance GEMM + argmin.
//   score(n,k) = ||cb_k||^2 - 2 x_n . cb_k   (x.x constant per row -> dropped)
// grid: NN/64 blocks, 256 threads (16x16), 64-node tile, 64-code chunks, BK=16.
// ============================================================
__global__ __launch_bounds__(256) void argmin_kernel(const float* __restrict__ x) {
    __shared__ float Xs[16][64];
    __shared__ float Cs[16][64];
    int tid = threadIdx.x, tx = tid & 15, ty = tid >> 4;
    int node0 = blockIdx.x * 64;
    float rm[4];
    int ri[4];
    #pragma unroll
    for (int i = 0; i < 4; i++) { rm[i] = 3.4e38f; ri[i] = 0x7fffffff; }

    for (int c0 = 0; c0 < KC; c0 += 64) {
        float acc[4][4] = {};
        for (int d0 = 0; d0 < DD; d0 += 16) {
            #pragma unroll
            for (int p = 0; p < 4; p++) {
                int e = tid + p * 256;
                int r = e >> 4, kk = e & 15;
                Xs[kk][r] = x[(size_t)(node0 + r)*DD + d0 + kk];
                Cs[kk][r] = g_ccb[(size_t)(c0 + r)*DD + d0 + kk];
            }
            __syncthreads();
            #pragma unroll
            for (int kk = 0; kk < 16; kk++) {
                float4 a = *(const float4*)&Xs[kk][ty*4];
                float4 b = *(const float4*)&Cs[kk][tx*4];
                float av[4] = {a.x, a.y, a.z, a.w};
                float bv[4] = {b.x, b.y, b.z, b.w};
                #pragma unroll
                for (int i = 0; i < 4; i++)
                    #pragma unroll
                    for (int j = 0; j < 4; j++)
                        acc[i][j] += av[i] * bv[j];
            }
            __syncthreads();
        }
        // local argmin (4 codes) -> reduce across the 16 tx lanes -> running min
        #pragma unroll
        for (int i = 0; i < 4; i++) {
            float bv = 3.4e38f;
            int bi = 0x7fffffff;
            #pragma unroll
            for (int j = 0; j < 4; j++) {
                int code = c0 + tx*4 + j;
                float s = g_cbn[code] - 2.f * acc[i][j];
                if (s < bv) { bv = s; bi = code; }   // j ascending: first index wins
            }
            #pragma unroll
            for (int off = 8; off >= 1; off >>= 1) {
                float ov = __shfl_xor_sync(~0u, bv, off);
                int   oi = __shfl_xor_sync(~0u, bi, off);
                if (ov < bv || (ov == bv && oi < bi)) { bv = ov; bi = oi; }
            }
            if (bv < rm[i] || (bv == rm[i] && bi < ri[i])) { rm[i] = bv; ri[i] = bi; }
        }
    }
    if (tx == 0) {
        #pragma unroll
        for (int i = 0; i < 4; i++) g_idx[node0 + ty*4 + i] = ri[i];
    }
}

// ============================================================
// K6: per node: copy x -> out, gather z = ct[idx] -> out, row inv-norms.
// grid NN blocks x 128 threads (float4 over D).
// ============================================================
__global__ void node_kernel(const float* __restrict__ x, float* __restrict__ out) {
    int n = blockIdx.x, t = threadIdx.x;
    float4 xv = ((const float4*)x)[(size_t)n*128 + t];
    ((float4*)(out + O_X))[(size_t)n*128 + t] = xv;
    int code = g_idx[n];
    float4 zv = ((const float4*)g_ct)[(size_t)code*128 + t];
    ((float4*)(out + O_Z))[(size_t)n*128 + t] = zv;
    float sx = xv.x*xv.x + xv.y*xv.y + xv.z*xv.z + xv.w*xv.w;
    float sz = zv.x*zv.x + zv.y*zv.y + zv.z*zv.z + zv.w*zv.w;
    #pragma unroll
    for (int off = 16; off; off >>= 1) {
        sx += __shfl_xor_sync(~0u, sx, off);
        sz += __shfl_xor_sync(~0u, sz, off);
    }
    __shared__ float rx[4], rz[4];
    if ((t & 31) == 0) { rx[t >> 5] = sx; rz[t >> 5] = sz; }
    __syncthreads();
    if (t == 0) {
        float nx = sqrtf(rx[0] + rx[1] + rx[2] + rx[3]);
        float nz = sqrtf(rz[0] + rz[1] + rz[2] + rz[3]);
        g_invnx[n] = 1.f / fmaxf(nx, 1e-12f);
        g_invnz[n] = 1.f / fmaxf(nz, 1e-12f);
    }
}

// ============================================================
// K7: per graph: pooled means + classifier heads (fused).
// grid GG blocks x 256 threads.
// ============================================================
__global__ __launch_bounds__(256) void pool_kernel(const float* __restrict__ x,
                                                   const float* __restrict__ clsw,
                                                   const float* __restrict__ clsb,
                                                   float* __restrict__ out) {
    int g = blockIdx.x, t = threadIdx.x;
    __shared__ int idxs[NPG];
    __shared__ float sp[3][DD];   // 0: pooled_causal, 1: pooled_counter, 2: pooled_x
    if (t < NPG) idxs[t] = g_idx[g*NPG + t];
    __syncthreads();
    for (int d = t; d < DD; d += 256) {
        float ax = 0.f, ac = 0.f, ak = 0.f;
        #pragma unroll 4
        for (int nn = 0; nn < NPG; nn++) {
            ax += x[(size_t)(g*NPG + nn)*DD + d];
            int c = idxs[nn];
            ac += g_ccb[(size_t)c*DD + d];
            ak += g_xcb[(size_t)c*DD + d];
        }
        float px = ax * (1.f/128.f);
        float pc = px + ac * (1.f/128.f);
        float pk = ak * (1.f/128.f);
        out[O_PX + (size_t)g*DD + d] = px;
        out[O_PC + (size_t)g*DD + d] = pc;
        sp[0][d] = pc; sp[1][d] = pk; sp[2][d] = px;
    }
    __syncthreads();
    int lane = t & 31, w = t >> 5;
    for (int job = w; job < 30; job += 8) {
        int vec = job / 10, cc = job % 10;
        float a = 0.f;
        for (int d = lane; d < DD; d += 32) a += sp[vec][d] * clsw[(size_t)cc*DD + d];
        #pragma unroll
        for (int off = 16; off; off >>= 1) a += __shfl_xor_sync(~0u, a, off);
        if (lane == 0) {
            long long base = (vec == 0) ? O_CPRE : (vec == 1 ? O_KPRE : O_YPRE);
            out[base + (size_t)g*TCLS + cc] = a + clsb[cc];
        }
    }
}

// ============================================================
// K8: per-graph adjacency: sigmoid( (Xn Xn^T) * 10 ), Xn = row-normalized.
// grid 2*GG (mode 0 = A_ori from x, mode 1 = A_rec from z in out buffer),
// 256 threads, 8x8 per thread, BK=16.
// ============================================================
__global__ __launch_bounds__(256) void adj_kernel(const float* __restrict__ x,
                                                  float* __restrict__ out) {
    int b = blockIdx.x;
    int mode = b >> 9;
    int g = b & 511;
    const float* src  = mode ? (out + O_Z) : x;
    const float* invn = mode ? g_invnz : g_invnx;
    float* dst = out + (mode ? O_AR : O_AO) + (size_t)g * (NPG*NPG);

    __shared__ float Ts[16][128];
    __shared__ float invs[NPG];
    int tid = threadIdx.x, tx = tid & 15, ty = tid >> 4;
    if (tid < NPG) invs[tid] = invn[g*NPG + tid];
    __syncthreads();

    float acc[8][8] = {};
    for (int d0 = 0; d0 < DD; d0 += 16) {
        #pragma unroll
        for (int p = 0; p < 8; p++) {
            int e = tid + p * 256;
            int r = e >> 4, kk = e & 15;
            Ts[kk][r] = src[(size_t)(g*NPG + r)*DD + d0 + kk] * invs[r];
        }
        __syncthreads();
        #pragma unroll
        for (int kk = 0; kk < 16; kk++) {
            float a[8], bb[8];
            float4 a0 = *(const float4*)&Ts[kk][ty*8];
            float4 a1 = *(const float4*)&Ts[kk][ty*8 + 4];
            a[0]=a0.x; a[1]=a0.y; a[2]=a0.z; a[3]=a0.w;
            a[4]=a1.x; a[5]=a1.y; a[6]=a1.z; a[7]=a1.w;
            #pragma unroll
            for (int j = 0; j < 8; j++) bb[j] = Ts[kk][tx + j*16];
            #pragma unroll
            for (int i = 0; i < 8; i++)
                #pragma unroll
                for (int j = 0; j < 8; j++)
                    acc[i][j] += a[i] * bb[j];
        }
        __syncthreads();
    }
    #pragma unroll
    for (int i = 0; i < 8; i++) {
        int r = ty*8 + i;
        #pragma unroll
        for (int j = 0; j < 8; j++) {
            int c = tx + j*16;
            dst[(size_t)r*NPG + c] = sigm(acc[i][j] * 10.f);   // /TEMP = *10
        }
    }
}

// ============================================================
extern "C" void kernel_launch(void* const* d_in, const int* in_sizes, int n_in,
                              void* d_out, int out_size) {
    const float* x      = (const float*)d_in[0];
    // d_in[1] = batch (deterministic: node n -> graph n/128); unused
    const float* cbin   = (const float*)d_in[2];
    const float* fc1w   = (const float*)d_in[3];
    const float* fc1b   = (const float*)d_in[4];
    const float* fc2w   = (const float*)d_in[5];
    const float* fc2b   = (const float*)d_in[6];
    const float* causal = (const float*)d_in[7];
    const float* clsw   = (const float*)d_in[8];
    const float* clsb   = (const float*)d_in[9];
    float* out = (float*)d_out;

    mlp_kernel<<<KC, 128>>>(cbin, fc1w, fc1b, fc2w, fc2b);
    diag_kernel<<<KC, 256>>>(causal, out);
    gemm_cc<<<dim3(8, 16), 256>>>(causal, 0);   // c1 = counter_matrix @ cs
    gemm_cc<<<dim3(8, 16), 256>>>(causal, 1);   // causal_cb
    gemm_cc<<<dim3(8, 16), 256>>>(causal, 2);   // counter_cb
    cbn_kernel<<<KC, 128>>>();
    argmin_kernel<<<NN / 64, 256>>>(x);
    node_kernel<<<NN, 128>>>(x, out);
    pool_kernel<<<GG, 256>>>(x, clsw, clsb, out);
    adj_kernel<<<2 * GG, 256>>>(x, out);
}

// round 2
// speedup vs baseline: 1.7135x; 1.7135x over previous
#include <cuda_runtime.h>
#include <math.h>

// ---- fixed problem shapes ----
#define GG   512      // graphs
#define NPG  128      // nodes per graph
#define NN   65536    // total nodes
#define DD   512      // feature dim
#define KC   1024     // codebook size
#define HHID 128      // mlp hidden
#define TCLS 10       // classes

// ---- device scratch (allocation-free workaround) ----
static __device__ float g_ct [KC*DD];   // codebook_transformed
static __device__ float g_cs [KC*DD];   // sigmoid(ct)
static __device__ float g_c1 [KC*DD];   // counter_matrix @ cs
static __device__ float g_ccb[KC*DD];   // causal_cb
static __device__ float g_xcb[KC*DD];   // counter_cb
static __device__ float g_cbn[KC];      // ||causal_cb_k||^2
static __device__ int   g_idx[NN];      // argmin code per node
static __device__ float g_invnx[NN];    // 1/max(||x_n||,1e-12)
static __device__ float g_invnz[NN];    // 1/max(||z_n||,1e-12)

// ---- output offsets (floats) in tuple order ----
#define O_CPRE 0LL
#define O_KPRE 5120LL
#define O_YPRE 10240LL
#define O_AO   15360LL
#define O_AR   8403968LL
#define O_Z    16792576LL
#define O_X    50347008LL
#define O_CD   83901440LL
#define O_CM   84950016LL
#define O_PC   85998592LL
#define O_PX   86260736LL

__device__ __forceinline__ float sigm(float v) { return 1.f / (1.f + expf(-v)); }
__device__ __forceinline__ float sigm10f(float v) { return 1.f / (1.f + __expf(-10.f * v)); }

// ---- f32x2 packed-FMA helpers (Blackwell FFMA2; ptxas never auto-emits) ----
__device__ __forceinline__ void ffma2(unsigned long long& d, unsigned long long a, unsigned long long b) {
    asm("fma.rn.f32x2 %0, %1, %2, %0;" : "+l"(d) : "l"(a), "l"(b));
}
__device__ __forceinline__ unsigned long long dup2(float v) {
    unsigned long long r;
    asm("mov.b64 %0, {%1, %1};" : "=l"(r) : "f"(v));
    return r;
}
__device__ __forceinline__ void unpk2(unsigned long long v, float& lo, float& hi) {
    asm("mov.b64 {%0, %1}, %2;" : "=f"(lo), "=f"(hi) : "l"(v));
}

// ============================================================
// K1: per-codebook-row 2-layer MLP: ct = fc2(sigmoid(fc1(cb))), cs = sigmoid(ct)
// ============================================================
__global__ void mlp_kernel(const float* __restrict__ cbin,
                           const float* __restrict__ fc1w, const float* __restrict__ fc1b,
                           const float* __restrict__ fc2w, const float* __restrict__ fc2b) {
    __shared__ float row[DD];
    __shared__ float hs[HHID];
    int k = blockIdx.x, t = threadIdx.x;
    for (int d = t; d < DD; d += 128) row[d] = cbin[(size_t)k*DD + d];
    __syncthreads();
    float acc = fc1b[t];
    const float* w = fc1w + (size_t)t*DD;
    #pragma unroll 8
    for (int d = 0; d < DD; d++) acc += row[d] * w[d];
    hs[t] = sigm(acc);
    __syncthreads();
    for (int d = t; d < DD; d += 128) {
        float a = fc2b[d];
        const float* w2 = fc2w + (size_t)d*HHID;
        #pragma unroll 8
        for (int h = 0; h < HHID; h++) a += hs[h] * w2[h];
        g_ct[(size_t)k*DD + d] = a;
        g_cs[(size_t)k*DD + d] = sigm(a);
    }
}

// ============================================================
// K2: write causal_diag (diag only) and counter_matrix (off-diag) outputs
// ============================================================
__global__ void diag_kernel(const float* __restrict__ causal, float* __restrict__ out) {
    int i = blockIdx.x;
    size_t base = (size_t)i * KC;
    for (int j = threadIdx.x; j < KC; j += blockDim.x) {
        float c = causal[base + j];
        bool dg = (j == i);
        out[O_CD + base + j] = dg ? c : 0.f;
        out[O_CM + base + j] = dg ? 0.f : c;
    }
}

// ============================================================
// K3: C[1024,512] = patch(causal) @ B, 64x64 tile, 4x4/thread, padded smem
// ============================================================
__global__ __launch_bounds__(256) void gemm_cc(const float* __restrict__ A, int mode) {
    const float* B = (mode == 2) ? g_c1 : g_cs;
    float* C = (mode == 0) ? g_c1 : (mode == 1 ? g_ccb : g_xcb);
    float diag_patch = (mode == 0) ? 0.f : 1.f;
    bool scale = (mode == 1);

    __shared__ __align__(16) float As[16][68];
    __shared__ __align__(16) float Bs[16][68];
    int tid = threadIdx.x, tx = tid & 15, ty = tid >> 4;
    int bm = blockIdx.y * 64, bn = blockIdx.x * 64;
    float acc[4][4] = {};
    for (int k0 = 0; k0 < KC; k0 += 16) {
        #pragma unroll
        for (int p = 0; p < 4; p++) {
            int e = tid + p * 256;
            int r = e >> 4, kk = e & 15;
            int grow = bm + r, gk = k0 + kk;
            As[kk][r] = (grow == gk) ? diag_patch : A[(size_t)grow*KC + gk];
        }
        #pragma unroll
        for (int p = 0; p < 4; p++) {
            int e = tid + p * 256;
            int kk = e >> 6, c = e & 63;
            int gk = k0 + kk;
            float bv = B[(size_t)gk*DD + bn + c];
            if (scale) bv *= A[(size_t)gk*KC + gk];
            Bs[kk][c] = bv;
        }
        __syncthreads();
        #pragma unroll
        for (int kk = 0; kk < 16; kk++) {
            float4 a = *(const float4*)&As[kk][ty*4];
            float4 b = *(const float4*)&Bs[kk][tx*4];
            float av[4] = {a.x, a.y, a.z, a.w};
            float bv[4] = {b.x, b.y, b.z, b.w};
            #pragma unroll
            for (int i = 0; i < 4; i++)
                #pragma unroll
                for (int j = 0; j < 4; j++)
                    acc[i][j] += av[i] * bv[j];
        }
        __syncthreads();
    }
    #pragma unroll
    for (int i = 0; i < 4; i++) {
        float4 v = make_float4(acc[i][0], acc[i][1], acc[i][2], acc[i][3]);
        *(float4*)&C[(size_t)(bm + ty*4 + i)*DD + bn + tx*4] = v;
    }
}

// ============================================================
// K4: g_cbn[k] = ||causal_cb_k||^2
// ============================================================
__global__ void cbn_kernel() {
    int k = blockIdx.x;
    float s = 0.f;
    for (int d = threadIdx.x; d < DD; d += 128) {
        float v = g_ccb[(size_t)k*DD + d];
        s += v * v;
    }
    #pragma unroll
    for (int off = 16; off; off >>= 1) s += __shfl_xor_sync(~0u, s, off);
    __shared__ float red[4];
    if ((threadIdx.x & 31) == 0) red[threadIdx.x >> 5] = s;
    __syncthreads();
    if (threadIdx.x == 0) g_cbn[k] = red[0] + red[1] + red[2] + red[3];
}

// ============================================================
// K5: fused distance GEMM + argmin, f32x2 microkernel.
// 128 nodes/block, 256 threads, 8x8 per thread (node pairs packed in f32x2).
// score(n,k) = ||cb_k||^2 - 2 x_n . cb_k
// ============================================================
__global__ __launch_bounds__(256, 2) void argmin_kernel(const float* __restrict__ x) {
    __shared__ __align__(16) float Xs[16][130];
    __shared__ __align__(16) float Cs[16][130];
    int tid = threadIdx.x, tx = tid & 15, ty = tid >> 4;
    int node0 = blockIdx.x * 128;

    float rm[8];
    int ri[8];
    #pragma unroll
    for (int i = 0; i < 8; i++) { rm[i] = 3.4e38f; ri[i] = 0x7fffffff; }

    for (int c0 = 0; c0 < KC; c0 += 128) {
        unsigned long long acc[4][8];
        #pragma unroll
        for (int i2 = 0; i2 < 4; i2++)
            #pragma unroll
            for (int j = 0; j < 8; j++) acc[i2][j] = 0ULL;

        for (int d0 = 0; d0 < DD; d0 += 16) {
            #pragma unroll
            for (int p = 0; p < 8; p++) {
                int e = tid + p * 256;
                int r = e >> 4, kk = e & 15;
                Xs[kk][r] = x[(size_t)(node0 + r)*DD + d0 + kk];
                Cs[kk][r] = g_ccb[(size_t)(c0 + r)*DD + d0 + kk];
            }
            __syncthreads();
            #pragma unroll
            for (int kk = 0; kk < 16; kk++) {
                unsigned long long av[4];
                #pragma unroll
                for (int i2 = 0; i2 < 4; i2++)
                    av[i2] = *(const unsigned long long*)&Xs[kk][ty*8 + i2*2];
                #pragma unroll
                for (int j = 0; j < 8; j++) {
                    unsigned long long bv = dup2(Cs[kk][tx + 16*j]);
                    #pragma unroll
                    for (int i2 = 0; i2 < 4; i2++) ffma2(acc[i2][j], av[i2], bv);
                }
            }
            __syncthreads();
        }

        // epilogue: per node-pair argmin over this thread's 8 codes, reduce over tx
        #pragma unroll
        for (int i2 = 0; i2 < 4; i2++) {
            float b0 = 3.4e38f, b1 = 3.4e38f;
            int i0 = 0x7fffffff, i1 = 0x7fffffff;
            #pragma unroll
            for (int j = 0; j < 8; j++) {
                int code = c0 + tx + 16*j;
                float cb2 = g_cbn[code];
                float lo, hi;
                unpk2(acc[i2][j], lo, hi);
                float s0 = cb2 - 2.f*lo;
                float s1 = cb2 - 2.f*hi;
                if (s0 < b0) { b0 = s0; i0 = code; }   // codes ascending in j
                if (s1 < b1) { b1 = s1; i1 = code; }
            }
            #pragma unroll
            for (int off = 1; off <= 8; off <<= 1) {
                float ov0 = __shfl_xor_sync(~0u, b0, off);
                int   oi0 = __shfl_xor_sync(~0u, i0, off);
                if (ov0 < b0 || (ov0 == b0 && oi0 < i0)) { b0 = ov0; i0 = oi0; }
                float ov1 = __shfl_xor_sync(~0u, b1, off);
                int   oi1 = __shfl_xor_sync(~0u, i1, off);
                if (ov1 < b1 || (ov1 == b1 && oi1 < i1)) { b1 = ov1; i1 = oi1; }
            }
            int n0 = 2*i2, n1 = 2*i2 + 1;
            if (b0 < rm[n0]) { rm[n0] = b0; ri[n0] = i0; }
            if (b1 < rm[n1]) { rm[n1] = b1; ri[n1] = i1; }
        }
    }
    if (tx == 0) {
        #pragma unroll
        for (int i = 0; i < 8; i++) g_idx[node0 + ty*8 + i] = ri[i];
    }
}

// ============================================================
// K6: per node: copy x -> out, gather z = ct[idx] -> out, row inv-norms.
// ============================================================
__global__ void node_kernel(const float* __restrict__ x, float* __restrict__ out) {
    int n = blockIdx.x, t = threadIdx.x;
    float4 xv = ((const float4*)x)[(size_t)n*128 + t];
    ((float4*)(out + O_X))[(size_t)n*128 + t] = xv;
    int code = g_idx[n];
    float4 zv = ((const float4*)g_ct)[(size_t)code*128 + t];
    ((float4*)(out + O_Z))[(size_t)n*128 + t] = zv;
    float sx = xv.x*xv.x + xv.y*xv.y + xv.z*xv.z + xv.w*xv.w;
    float sz = zv.x*zv.x + zv.y*zv.y + zv.z*zv.z + zv.w*zv.w;
    #pragma unroll
    for (int off = 16; off; off >>= 1) {
        sx += __shfl_xor_sync(~0u, sx, off);
        sz += __shfl_xor_sync(~0u, sz, off);
    }
    __shared__ float rx[4], rz[4];
    if ((t & 31) == 0) { rx[t >> 5] = sx; rz[t >> 5] = sz; }
    __syncthreads();
    if (t == 0) {
        float nx = sqrtf(rx[0] + rx[1] + rx[2] + rx[3]);
        float nz = sqrtf(rz[0] + rz[1] + rz[2] + rz[3]);
        g_invnx[n] = 1.f / fmaxf(nx, 1e-12f);
        g_invnz[n] = 1.f / fmaxf(nz, 1e-12f);
    }
}

// ============================================================
// K7: per graph: pooled means + classifier heads (fused).
// ============================================================
__global__ __launch_bounds__(256) void pool_kernel(const float* __restrict__ x,
                                                   const float* __restrict__ clsw,
                                                   const float* __restrict__ clsb,
                                                   float* __restrict__ out) {
    int g = blockIdx.x, t = threadIdx.x;
    __shared__ int idxs[NPG];
    __shared__ float sp[3][DD];
    if (t < NPG) idxs[t] = g_idx[g*NPG + t];
    __syncthreads();
    for (int d = t; d < DD; d += 256) {
        float ax = 0.f, ac = 0.f, ak = 0.f;
        #pragma unroll 4
        for (int nn = 0; nn < NPG; nn++) {
            ax += x[(size_t)(g*NPG + nn)*DD + d];
            int c = idxs[nn];
            ac += g_ccb[(size_t)c*DD + d];
            ak += g_xcb[(size_t)c*DD + d];
        }
        float px = ax * (1.f/128.f);
        float pc = px + ac * (1.f/128.f);
        float pk = ak * (1.f/128.f);
        out[O_PX + (size_t)g*DD + d] = px;
        out[O_PC + (size_t)g*DD + d] = pc;
        sp[0][d] = pc; sp[1][d] = pk; sp[2][d] = px;
    }
    __syncthreads();
    int lane = t & 31, w = t >> 5;
    for (int job = w; job < 30; job += 8) {
        int vec = job / 10, cc = job % 10;
        float a = 0.f;
        for (int d = lane; d < DD; d += 32) a += sp[vec][d] * clsw[(size_t)cc*DD + d];
        #pragma unroll
        for (int off = 16; off; off >>= 1) a += __shfl_xor_sync(~0u, a, off);
        if (lane == 0) {
            long long base = (vec == 0) ? O_CPRE : (vec == 1 ? O_KPRE : O_YPRE);
            out[base + (size_t)g*TCLS + cc] = a + clsb[cc];
        }
    }
}

// ============================================================
// K8: per-graph adjacency: sigmoid(Gram * 10), f32x2 microkernel.
// grid 2*GG (mode 0 = A_ori from x, mode 1 = A_rec from z), 256 threads.
// ============================================================
__global__ __launch_bounds__(256, 2) void adj_kernel(const float* __restrict__ x,
                                                     float* __restrict__ out) {
    int b = blockIdx.x;
    int mode = b >> 9;
    int g = b & 511;
    const float* src  = mode ? (out + O_Z) : x;
    const float* invn = mode ? g_invnz : g_invnx;
    float* dst = out + (mode ? O_AR : O_AO) + (size_t)g * (NPG*NPG);

    __shared__ __align__(16) float Ts[16][130];
    __shared__ float invs[NPG];
    int tid = threadIdx.x, tx = tid & 15, ty = tid >> 4;
    if (tid < NPG) invs[tid] = invn[g*NPG + tid];
    __syncthreads();

    unsigned long long acc[4][8];
    #pragma unroll
    for (int i2 = 0; i2 < 4; i2++)
        #pragma unroll
        for (int j = 0; j < 8; j++) acc[i2][j] = 0ULL;

    for (int d0 = 0; d0 < DD; d0 += 16) {
        #pragma unroll
        for (int p = 0; p < 8; p++) {
            int e = tid + p * 256;
            int r = e >> 4, kk = e & 15;
            Ts[kk][r] = src[(size_t)(g*NPG + r)*DD + d0 + kk] * invs[r];
        }
        __syncthreads();
        #pragma unroll
        for (int kk = 0; kk < 16; kk++) {
            unsigned long long av[4];
            #pragma unroll
            for (int i2 = 0; i2 < 4; i2++)
                av[i2] = *(const unsigned long long*)&Ts[kk][ty*8 + i2*2];
            #pragma unroll
            for (int j = 0; j < 8; j++) {
                unsigned long long bv = dup2(Ts[kk][tx + 16*j]);
                #pragma unroll
                for (int i2 = 0; i2 < 4; i2++) ffma2(acc[i2][j], av[i2], bv);
            }
        }
        __syncthreads();
    }
    #pragma unroll
    for (int i2 = 0; i2 < 4; i2++) {
        int r0 = ty*8 + 2*i2, r1 = r0 + 1;
        #pragma unroll
        for (int j = 0; j < 8; j++) {
            int c = tx + 16*j;
            float lo, hi;
            unpk2(acc[i2][j], lo, hi);
            dst[(size_t)r0*NPG + c] = sigm10f(lo);
            dst[(size_t)r1*NPG + c] = sigm10f(hi);
        }
    }
}

// ============================================================
extern "C" void kernel_launch(void* const* d_in, const int* in_sizes, int n_in,
                              void* d_out, int out_size) {
    const float* x      = (const float*)d_in[0];
    const float* cbin   = (const float*)d_in[2];
    const float* fc1w   = (const float*)d_in[3];
    const float* fc1b   = (const float*)d_in[4];
    const float* fc2w   = (const float*)d_in[5];
    const float* fc2b   = (const float*)d_in[6];
    const float* causal = (const float*)d_in[7];
    const float* clsw   = (const float*)d_in[8];
    const float* clsb   = (const float*)d_in[9];
    float* out = (float*)d_out;

    mlp_kernel<<<KC, 128>>>(cbin, fc1w, fc1b, fc2w, fc2b);
    diag_kernel<<<KC, 256>>>(causal, out);
    gemm_cc<<<dim3(8, 16), 256>>>(causal, 0);   // c1 = counter_matrix @ cs
    gemm_cc<<<dim3(8, 16), 256>>>(causal, 1);   // causal_cb
    gemm_cc<<<dim3(8, 16), 256>>>(causal, 2);   // counter_cb
    cbn_kernel<<<KC, 128>>>();
    argmin_kernel<<<NN / 128, 256>>>(x);
    node_kernel<<<NN, 128>>>(x, out);
    pool_kernel<<<GG, 256>>>(x, clsw, clsb, out);
    adj_kernel<<<2 * GG, 256>>>(x, out);
}